// round 12
// baseline (speedup 1.0000x reference)
#include <cuda_runtime.h>

// DRNN: two stacked SimpleRNN(tanh), round 9. B=512, T=512, D=64, H=100.
//
// Kernel 1 (xp_prepass v2): XP[b,t,u] = x_{b,t}.W1x[:,u] + b1[u], all t in
//   parallel. 4-timestep ILP: each broadcast LDS.128 feeds 16 FFMA2 (1:8),
//   8 independent accumulator chains -> latency actually hidden.
//
// Kernel 2 (mainloop): persistent per-CTA RNN. 128 CTAs x 4 rows, 384 thr
//   = 12 warps, UNIFORM 1 unit/lane, full k-columns (50 u64 = ~100 wregs):
//   G1  (wid 0-3):  h1_i    = tanh(xp_i + W1h.h1_{i-1})
//   G2a (wid 4-7):  p_{i-1} = W2x.h1_{i-1} + b2
//   G2b (wid 8-11): h2_{i-2}= tanh(p_{i-2} + W2h.h2_{i-3})
//   SMSP s carries exactly one warp of each group: 600 FFMA2/SMSP/step
//   (balanced 1200-cyc FMA floor) with THREE warps/SMSP to hide LDS latency
//   (was two). Uniform ~130 regs/thread fits 384 thr in the 64K RF.
// Pairwise named barriers: bar2 = G1+G2a (256 thr), bar3 = G2a+G2b (256 thr).
// fma.rn.f32x2 packs 2 MACs/instr; broadcast LDS.128; no shuffles.

#define TT   512
#define BB   512
#define DD   64
#define HH   100
#define ROWS 4
#define HSR  104    // h/p row stride (25 quads exact + 16B-align pad)
#define NTHR 384

#define BAR_SYNC(id, cnt) asm volatile("bar.sync %0, %1;" :: "r"(id), "r"(cnt) : "memory")

__device__ float XPbuf[(size_t)BB * TT * HH];   // 104.8 MB scratch

__device__ __forceinline__ void ffma2(unsigned long long &acc,
                                      unsigned long long a,
                                      unsigned long long b) {
    asm("fma.rn.f32x2 %0, %1, %2, %0;" : "+l"(acc) : "l"(a), "l"(b));
}

__device__ __forceinline__ unsigned long long pack2(float lo, float hi) {
    unsigned long long r;
    asm("mov.b64 %0, {%1, %2};" : "=l"(r) : "f"(lo), "f"(hi));
    return r;
}

__device__ __forceinline__ float hsum2(unsigned long long v) {
    float lo, hi;
    asm("mov.b64 {%0, %1}, %2;" : "=f"(lo), "=f"(hi) : "l"(v));
    return lo + hi;
}

__device__ __forceinline__ ulonglong2 lds128(const float* p) {
    return *reinterpret_cast<const ulonglong2*>(p);
}

// tanh via exp + fast divide: ~1e-7 rel err.
__device__ __forceinline__ float tanh_f(float x) {
    float ax = fabsf(x);
    float e  = __expf(-2.0f * ax);
    float r  = __fdividef(1.0f - e, 1.0f + e);
    return copysignf(r, x);
}

// ───────────────────────── Kernel 1: XP pre-pass v2 ──────────────────────
// grid (4, 512): blockIdx.x = 128-timestep block, blockIdx.y = batch row.
// 256 thr: iu = tid&63 -> units (2iu, 2iu+1); tg = tid>>6 -> 32 timesteps,
// processed in 8 blocks of 4 t (each LDS.128 feeds 16 FFMA2, 8 acc chains).
__global__ __launch_bounds__(256, 1)
void xp_prepass(const float* __restrict__ X, const float* __restrict__ W1x,
                const float* __restrict__ B1)
{
    __shared__ __align__(16) float sXT[128][DD];   // 32 KB x-tile

    const int b   = blockIdx.y;
    const int tb  = blockIdx.x;
    const int tid = threadIdx.x;
    const int iu  = tid & 63;
    const int tg  = tid >> 6;
    const bool act = (iu < 50);
    const int u0  = act ? 2 * iu : 98;

    unsigned long long w[64];
    #pragma unroll
    for (int q = 0; q < 16; ++q) {
        int k = 4 * q;
        w[4*q+0] = pack2(W1x[(k  )*HH + u0  ], W1x[(k+1)*HH + u0  ]);
        w[4*q+1] = pack2(W1x[(k+2)*HH + u0  ], W1x[(k+3)*HH + u0  ]);
        w[4*q+2] = pack2(W1x[(k  )*HH + u0+1], W1x[(k+1)*HH + u0+1]);
        w[4*q+3] = pack2(W1x[(k+2)*HH + u0+1], W1x[(k+3)*HH + u0+1]);
    }
    const float bj0 = B1[u0], bj1 = B1[u0 + 1];

    for (int s = tid; s < 128 * DD; s += 256) {
        int t = s >> 6, k = s & 63;
        sXT[t][k] = X[((size_t)b * TT + tb * 128 + t) * DD + k];
    }
    __syncthreads();

    #pragma unroll
    for (int blk = 0; blk < 8; ++blk) {
        const int t = tg * 32 + blk * 4;
        unsigned long long a[8];                   // [0..3]=u0 t0..3, [4..7]=u1
        #pragma unroll
        for (int n = 0; n < 8; ++n) a[n] = 0ull;
        #pragma unroll
        for (int it = 0; it < 16; ++it) {
            ulonglong2 v0 = lds128(&sXT[t + 0][4 * it]);
            ulonglong2 v1 = lds128(&sXT[t + 1][4 * it]);
            ulonglong2 v2 = lds128(&sXT[t + 2][4 * it]);
            ulonglong2 v3 = lds128(&sXT[t + 3][4 * it]);
            unsigned long long wA0 = w[4*it+0], wB0 = w[4*it+1];
            unsigned long long wA1 = w[4*it+2], wB1 = w[4*it+3];
            ffma2(a[0], v0.x, wA0); ffma2(a[4], v0.x, wA1);
            ffma2(a[1], v1.x, wA0); ffma2(a[5], v1.x, wA1);
            ffma2(a[2], v2.x, wA0); ffma2(a[6], v2.x, wA1);
            ffma2(a[3], v3.x, wA0); ffma2(a[7], v3.x, wA1);
            ffma2(a[0], v0.y, wB0); ffma2(a[4], v0.y, wB1);
            ffma2(a[1], v1.y, wB0); ffma2(a[5], v1.y, wB1);
            ffma2(a[2], v2.y, wB0); ffma2(a[6], v2.y, wB1);
            ffma2(a[3], v3.y, wB0); ffma2(a[7], v3.y, wB1);
        }
        if (act) {
            #pragma unroll
            for (int q = 0; q < 4; ++q) {
                float2 r;
                r.x = hsum2(a[q])     + bj0;
                r.y = hsum2(a[4 + q]) + bj1;
                *reinterpret_cast<float2*>(
                    &XPbuf[((size_t)b * TT + tb * 128 + t + q) * HH + u0]) = r;
            }
        }
    }
}

// ───────────────────────── Kernel 2: main recurrence ─────────────────────

// Single-unit accumulate: acc[r], r = row 0..3. 4 LDS -> 8 FFMA2 per iter.
__device__ __forceinline__ void accum4_h(unsigned long long (&acc)[4],
                                         const float* base,
                                         const unsigned long long* w)
{
    #pragma unroll
    for (int it = 0; it < 25; ++it) {
        ulonglong2 v0 = lds128(base + 0*HSR + 4*it);
        ulonglong2 v1 = lds128(base + 1*HSR + 4*it);
        ulonglong2 v2 = lds128(base + 2*HSR + 4*it);
        ulonglong2 v3 = lds128(base + 3*HSR + 4*it);
        unsigned long long wA = w[2*it];
        unsigned long long wB = w[2*it + 1];
        ffma2(acc[0], v0.x, wA); ffma2(acc[1], v1.x, wA);
        ffma2(acc[2], v2.x, wA); ffma2(acc[3], v3.x, wA);
        ffma2(acc[0], v0.y, wB); ffma2(acc[1], v1.y, wB);
        ffma2(acc[2], v2.y, wB); ffma2(acc[3], v3.y, wB);
    }
}

__global__ __launch_bounds__(NTHR, 1)
void drnn_kernel(const float* __restrict__ W1h,
                 const float* __restrict__ W2x, const float* __restrict__ W2h,
                 const float* __restrict__ B2,
                 const float* __restrict__ Wo,  const float* __restrict__ Bo,
                 float* __restrict__ out)
{
    __shared__ __align__(16) float sH1[2][ROWS][HSR];
    __shared__ __align__(16) float sH2[2][ROWS][HSR];
    __shared__ __align__(16) float sP [2][ROWS][HSR];   // p = W2x.h1 + b2

    const int tid  = threadIdx.x;
    const int wid  = tid >> 5;
    const int lane = tid & 31;
    const int r0   = blockIdx.x * ROWS;
    // gid: 0 = G1 (wid 0-3), 1 = G2a (wid 4-7), 2 = G2b (wid 8-11).
    const int gid  = wid >> 2;
    // Unit: one full column per lane, wid&3 = SMSP id = unit block.
    const int u    = (wid & 3) * 32 + lane;              // 0..127
    const bool act = (u < HH);
    const int uc   = act ? u : (HH - 1);

    unsigned long long w[50];
    float bj = 0.f;
    {
        const float* Wsrc = (gid == 0) ? W1h : ((gid == 1) ? W2x : W2h);
        #pragma unroll
        for (int q = 0; q < 25; ++q) {
            int k = 4 * q;
            w[2*q]   = pack2(Wsrc[(k  )*HH + uc], Wsrc[(k+1)*HH + uc]);
            w[2*q+1] = pack2(Wsrc[(k+2)*HH + uc], Wsrc[(k+3)*HH + uc]);
        }
        if (gid == 1) bj = B2[uc];                       // b2 folded into p
    }

    // Zero state rings (h1_{-1} = h2_{-1} = ... = 0; pads finite-0).
    {
        float* z1 = &sH1[0][0][0];
        for (int idx = tid; idx < 2*ROWS*HSR; idx += NTHR) z1[idx] = 0.f;
        float* z2 = &sH2[0][0][0];
        for (int idx = tid; idx < 2*ROWS*HSR; idx += NTHR) z2[idx] = 0.f;
    }
    __syncthreads();

    // G1: register xp ring, preload xp_0 (prepass is stream-ordered before us).
    float xcur[4];
    if (gid == 0) {
        #pragma unroll
        for (int r = 0; r < ROWS; ++r)
            xcur[r] = XPbuf[((size_t)(r0 + r) * TT + 0) * HH + uc];
    }

    // Wall-step i: G1 -> h1_i, G2a -> p_{i-1}, G2b -> h2_{i-2}.
    //   bar 2: G1+G2a (h1 handoff)                [256 thr]
    //   bar 3: G2a+G2b (p handoff, sH2 self-ring) [256 thr]
    for (int i = 0; i <= TT + 1; ++i) {
        const int pc = i & 1, pn = pc ^ 1;
        if (gid == 0) {
            if (i <= TT - 1) {                           // h1_i
                float xn[4];
                const bool pf = (i + 1 <= TT - 1);
                if (pf) {
                    #pragma unroll
                    for (int r = 0; r < ROWS; ++r)
                        xn[r] = XPbuf[((size_t)(r0 + r) * TT + (i+1)) * HH + uc];
                }
                unsigned long long a[4] = {0ull, 0ull, 0ull, 0ull};
                accum4_h(a, &sH1[pn][0][0], w);
                if (act) {
                    #pragma unroll
                    for (int r = 0; r < ROWS; ++r)
                        sH1[pc][r][u] = tanh_f(hsum2(a[r]) + xcur[r]);
                }
                if (pf) {
                    #pragma unroll
                    for (int r = 0; r < ROWS; ++r) xcur[r] = xn[r];
                }
            }
            BAR_SYNC(2, 256);
        } else if (gid == 1) {
            if (i >= 1 && i <= TT) {                     // p_{i-1}
                unsigned long long a[4] = {0ull, 0ull, 0ull, 0ull};
                accum4_h(a, &sH1[pn][0][0], w);
                if (act) {
                    #pragma unroll
                    for (int r = 0; r < ROWS; ++r)
                        sP[pn][r][u] = hsum2(a[r]) + bj;
                }
            }
            BAR_SYNC(3, 256);   // release G2b first (longer consumer chain)
            BAR_SYNC(2, 256);
        } else {
            if (i >= 2) {                                // h2_{i-2}
                float pv[4];
                #pragma unroll
                for (int r = 0; r < ROWS; ++r)
                    pv[r] = sP[pc][r][uc];               // hoisted (since bar3)
                unsigned long long a[4] = {0ull, 0ull, 0ull, 0ull};
                accum4_h(a, &sH2[pn][0][0], w);
                if (act) {
                    #pragma unroll
                    for (int r = 0; r < ROWS; ++r)
                        sH2[pc][r][u] = tanh_f(hsum2(a[r]) + pv[r]);
                }
            }
            BAR_SYNC(3, 256);
        }
    }
    __syncthreads();

    // h1_511 in sH1[1], h2_511 in sH2[1] (both at parity 1).
    float* outVec = out;                      // [512]
    float* outH1  = out + BB;                 // [512,100]
    float* outH2  = out + BB + BB*HH;         // [512,100]

    for (int idx = tid; idx < ROWS*HH; idx += NTHR) {
        int r = idx / HH, uu = idx % HH;
        outH1[(size_t)(r0 + r)*HH + uu] = sH1[1][r][uu];
        outH2[(size_t)(r0 + r)*HH + uu] = sH2[1][r][uu];
    }

    // Output head: out[r] = h2_T[r] . Wo + bo  (warp 0).
    if (tid < 32) {
        #pragma unroll
        for (int r = 0; r < ROWS; ++r) {
            float v = 0.f;
            #pragma unroll
            for (int mm = 0; mm < 4; ++mm) {
                int uu = mm*32 + tid;
                if (uu < HH) v += sH2[1][r][uu] * Wo[uu];
            }
            #pragma unroll
            for (int off = 16; off; off >>= 1)
                v += __shfl_down_sync(0xffffffffu, v, off);
            if (tid == 0) outVec[r0 + r] = v + Bo[0];
        }
    }
}

extern "C" void kernel_launch(void* const* d_in, const int* in_sizes, int n_in,
                              void* d_out, int out_size) {
    (void)in_sizes; (void)n_in; (void)out_size;
    const float* X   = (const float*)d_in[0];
    const float* W1x = (const float*)d_in[1];
    const float* W1h = (const float*)d_in[2];
    const float* B1  = (const float*)d_in[3];
    const float* W2x = (const float*)d_in[4];
    const float* W2h = (const float*)d_in[5];
    const float* B2  = (const float*)d_in[6];
    const float* Wo  = (const float*)d_in[7];
    const float* Bo  = (const float*)d_in[8];

    dim3 pgrid(4, BB);
    xp_prepass<<<pgrid, 256>>>(X, W1x, B1);
    drnn_kernel<<<BB/ROWS, NTHR>>>(W1h, W2x, W2h, B2, Wo, Bo, (float*)d_out);
}

// round 13
// speedup vs baseline: 1.1287x; 1.1287x over previous
#include <cuda_runtime.h>

// DRNN: two stacked SimpleRNN(tanh), round 10. B=512, T=512, D=64, H=100.
//
// Kernel 1 (xp_prepass v3): XP[b,t,u] = x_{b,t}.W1x[:,u] + b1[u], all t.
//   FIXED occupancy: 1 unit/lane -> ~100 regs, __launch_bounds__(256,2)
//   gives 2 CTAs/SM (R11 version sat at 1). 128-t tile, float4 tile loads,
//   4-t ILP accumulator blocks.
//
// Kernel 2 (mainloop): persistent per-CTA RNN. 128 CTAs x 4 rows, 256 thr
//   = 8 warps, ALL 2 units/lane (100 u64 wregs), LDS/step = 600 (was 800):
//   G1  (wid 0-3): h1_i = tanh(xp_i + W1h.h1_{i-1})   ROW-SPLIT: each warp
//        does 2 rows x 64-unit half -> 50 LDS + 200 FFMA2 (short serial path)
//   G2a (wid 4,5): p_{i-1} = W2x.h1_{i-1} + b2        4 rows, unit-halved
//   G2b (wid 6,7): h2_{i-2}= tanh(p_{i-2} + W2h.h2_{i-3})
//   SMSP s (= wid&3): exactly 600 FFMA2 + 150 LDS -> balanced 1200-cyc floor.
// Pairwise named barriers: bar2 = G1+G2a (192 thr), bar3 = G2a+G2b (128 thr).
// fma.rn.f32x2 packs 2 MACs/instr; broadcast LDS.128; no shuffles.

#define TT   512
#define BB   512
#define DD   64
#define HH   100
#define ROWS 4
#define HSR  104    // h/p row stride
#define NTHR 256

#define BAR_SYNC(id, cnt) asm volatile("bar.sync %0, %1;" :: "r"(id), "r"(cnt) : "memory")

__device__ float XPbuf[(size_t)BB * TT * HH];   // 104.8 MB scratch

__device__ __forceinline__ void ffma2(unsigned long long &acc,
                                      unsigned long long a,
                                      unsigned long long b) {
    asm("fma.rn.f32x2 %0, %1, %2, %0;" : "+l"(acc) : "l"(a), "l"(b));
}

__device__ __forceinline__ unsigned long long pack2(float lo, float hi) {
    unsigned long long r;
    asm("mov.b64 %0, {%1, %2};" : "=l"(r) : "f"(lo), "f"(hi));
    return r;
}

__device__ __forceinline__ float hsum2(unsigned long long v) {
    float lo, hi;
    asm("mov.b64 {%0, %1}, %2;" : "=f"(lo), "=f"(hi) : "l"(v));
    return lo + hi;
}

__device__ __forceinline__ ulonglong2 lds128(const float* p) {
    return *reinterpret_cast<const ulonglong2*>(p);
}

// tanh via exp + fast divide: ~1e-7 rel err.
__device__ __forceinline__ float tanh_f(float x) {
    float ax = fabsf(x);
    float e  = __expf(-2.0f * ax);
    float r  = __fdividef(1.0f - e, 1.0f + e);
    return copysignf(r, x);
}

// ───────────────────────── Kernel 1: XP pre-pass v3 ──────────────────────
// grid (4, 512): blockIdx.x = 128-timestep tile, blockIdx.y = batch row.
// 256 thr = 2 t-groups x 128 unit-lanes (1 unit/lane, 100 active).
// Per thread: 64 t in 16 blocks of 4 (4 indep accumulator chains).
__global__ __launch_bounds__(256, 2)
void xp_prepass(const float* __restrict__ X, const float* __restrict__ W1x,
                const float* __restrict__ B1)
{
    __shared__ __align__(16) float sXT[128][DD];   // 32 KB x-tile

    const int b   = blockIdx.y;
    const int tb  = blockIdx.x;
    const int tid = threadIdx.x;
    const int iu  = tid & 127;
    const int tg  = tid >> 7;                       // 0/1 -> 64 t each
    const bool act = (iu < HH);
    const int uc  = act ? iu : (HH - 1);

    unsigned long long w[32];                       // W1x column uc
    #pragma unroll
    for (int q = 0; q < 16; ++q) {
        int k = 4 * q;
        w[2*q]   = pack2(W1x[(k  )*HH + uc], W1x[(k+1)*HH + uc]);
        w[2*q+1] = pack2(W1x[(k+2)*HH + uc], W1x[(k+3)*HH + uc]);
    }
    const float bj = B1[uc];

    // Vectorized tile load: 8192 floats = 2048 float4.
    {
        const float4* xsrc = reinterpret_cast<const float4*>(
            X + ((size_t)b * TT + tb * 128) * DD);
        float4* dst = reinterpret_cast<float4*>(&sXT[0][0]);
        #pragma unroll
        for (int s = 0; s < 8; ++s)
            dst[tid + 256 * s] = xsrc[tid + 256 * s];
    }
    __syncthreads();

    #pragma unroll 4
    for (int blk = 0; blk < 16; ++blk) {
        const int t = tg * 64 + blk * 4;
        unsigned long long a[4];
        #pragma unroll
        for (int n = 0; n < 4; ++n) a[n] = 0ull;
        #pragma unroll
        for (int it = 0; it < 16; ++it) {
            ulonglong2 v0 = lds128(&sXT[t + 0][4 * it]);
            ulonglong2 v1 = lds128(&sXT[t + 1][4 * it]);
            ulonglong2 v2 = lds128(&sXT[t + 2][4 * it]);
            ulonglong2 v3 = lds128(&sXT[t + 3][4 * it]);
            unsigned long long wA = w[2*it], wB = w[2*it + 1];
            ffma2(a[0], v0.x, wA); ffma2(a[1], v1.x, wA);
            ffma2(a[2], v2.x, wA); ffma2(a[3], v3.x, wA);
            ffma2(a[0], v0.y, wB); ffma2(a[1], v1.y, wB);
            ffma2(a[2], v2.y, wB); ffma2(a[3], v3.y, wB);
        }
        if (act) {
            #pragma unroll
            for (int q = 0; q < 4; ++q)
                XPbuf[((size_t)b * TT + tb * 128 + t + q) * HH + uc]
                    = hsum2(a[q]) + bj;
        }
    }
}

// ───────────────────────── Kernel 2: main recurrence ─────────────────────

// G2 accumulate: 4 rows x 2 units. acc[r]=unit0, acc[4+r]=unit1.
__device__ __forceinline__ void accum8_h(unsigned long long (&acc)[8],
                                         const float* base,
                                         const unsigned long long* w)
{
    #pragma unroll
    for (int it = 0; it < 25; ++it) {
        ulonglong2 v0 = lds128(base + 0*HSR + 4*it);
        ulonglong2 v1 = lds128(base + 1*HSR + 4*it);
        ulonglong2 v2 = lds128(base + 2*HSR + 4*it);
        ulonglong2 v3 = lds128(base + 3*HSR + 4*it);
        unsigned long long wA0 = w[4*it + 0];
        unsigned long long wB0 = w[4*it + 1];
        unsigned long long wA1 = w[4*it + 2];
        unsigned long long wB1 = w[4*it + 3];
        ffma2(acc[0], v0.x, wA0); ffma2(acc[4], v0.x, wA1);
        ffma2(acc[1], v1.x, wA0); ffma2(acc[5], v1.x, wA1);
        ffma2(acc[2], v2.x, wA0); ffma2(acc[6], v2.x, wA1);
        ffma2(acc[3], v3.x, wA0); ffma2(acc[7], v3.x, wA1);
        ffma2(acc[0], v0.y, wB0); ffma2(acc[4], v0.y, wB1);
        ffma2(acc[1], v1.y, wB0); ffma2(acc[5], v1.y, wB1);
        ffma2(acc[2], v2.y, wB0); ffma2(acc[6], v2.y, wB1);
        ffma2(acc[3], v3.y, wB0); ffma2(acc[7], v3.y, wB1);
    }
}

// G1 accumulate: 2 rows x 2 units. acc = {r0u0, r1u0, r0u1, r1u1}.
__device__ __forceinline__ void accum4_g1(unsigned long long (&acc)[4],
                                          const float* base,
                                          const unsigned long long* w)
{
    #pragma unroll
    for (int it = 0; it < 25; ++it) {
        ulonglong2 v0 = lds128(base + 0*HSR + 4*it);
        ulonglong2 v1 = lds128(base + 1*HSR + 4*it);
        unsigned long long wA0 = w[4*it + 0];
        unsigned long long wB0 = w[4*it + 1];
        unsigned long long wA1 = w[4*it + 2];
        unsigned long long wB1 = w[4*it + 3];
        ffma2(acc[0], v0.x, wA0); ffma2(acc[1], v1.x, wA0);
        ffma2(acc[2], v0.x, wA1); ffma2(acc[3], v1.x, wA1);
        ffma2(acc[0], v0.y, wB0); ffma2(acc[1], v1.y, wB0);
        ffma2(acc[2], v0.y, wB1); ffma2(acc[3], v1.y, wB1);
    }
}

__global__ __launch_bounds__(NTHR, 1)
void drnn_kernel(const float* __restrict__ W1h,
                 const float* __restrict__ W2x, const float* __restrict__ W2h,
                 const float* __restrict__ B2,
                 const float* __restrict__ Wo,  const float* __restrict__ Bo,
                 float* __restrict__ out)
{
    __shared__ __align__(16) float sH1[2][ROWS][HSR];
    __shared__ __align__(16) float sH2[2][ROWS][HSR];
    __shared__ __align__(16) float sP [2][ROWS][HSR];   // p = W2x.h1 + b2

    const int tid  = threadIdx.x;
    const int wid  = tid >> 5;
    const int lane = tid & 31;
    const int r0   = blockIdx.x * ROWS;
    // gid: 0 = G1 (wid 0-3), 1 = G2a (wid 4,5), 2 = G2b (wid 6,7).
    const int gid  = (wid < 4) ? 0 : ((wid < 6) ? 1 : 2);
    // Unit half (all groups): uh = wid&1 -> units [0:64) or [64:100).
    const int uh   = wid & 1;
    const int u0r  = uh * 64 + 2 * lane;
    const bool act = (u0r < HH);
    const int u0   = act ? u0r : (HH - 2);     // clamped, keeps u0+1 <= 99
    // G1 row pair: rp = (wid>>1)&1 -> rows {0,1} or {2,3}.
    const int rp   = (wid >> 1) & 1;

    unsigned long long w[100];
    float bj0 = 0.f, bj1 = 0.f;
    {
        const float* Wsrc = (gid == 0) ? W1h : ((gid == 1) ? W2x : W2h);
        #pragma unroll
        for (int q = 0; q < 25; ++q) {
            int k = 4 * q;
            w[4*q+0] = pack2(Wsrc[(k  )*HH + u0  ], Wsrc[(k+1)*HH + u0  ]);
            w[4*q+1] = pack2(Wsrc[(k+2)*HH + u0  ], Wsrc[(k+3)*HH + u0  ]);
            w[4*q+2] = pack2(Wsrc[(k  )*HH + u0+1], Wsrc[(k+1)*HH + u0+1]);
            w[4*q+3] = pack2(Wsrc[(k+2)*HH + u0+1], Wsrc[(k+3)*HH + u0+1]);
        }
        if (gid == 1) { bj0 = B2[u0]; bj1 = B2[u0 + 1]; }
    }

    // Zero state rings.
    {
        float* z1 = &sH1[0][0][0];
        for (int idx = tid; idx < 2*ROWS*HSR; idx += NTHR) z1[idx] = 0.f;
        float* z2 = &sH2[0][0][0];
        for (int idx = tid; idx < 2*ROWS*HSR; idx += NTHR) z2[idx] = 0.f;
    }
    __syncthreads();

    // G1: register xp ring (float2 = units u0,u0+1 per row), preload xp_0.
    float2 xcur[2];
    if (gid == 0) {
        #pragma unroll
        for (int r = 0; r < 2; ++r)
            xcur[r] = *reinterpret_cast<const float2*>(
                &XPbuf[((size_t)(r0 + rp*2 + r) * TT + 0) * HH + u0]);
    }

    // Wall-step i: G1 -> h1_i, G2a -> p_{i-1}, G2b -> h2_{i-2}.
    //   bar 2: G1+G2a (h1 handoff)                [192 thr]
    //   bar 3: G2a+G2b (p handoff, sH2 self-ring) [128 thr]
    for (int i = 0; i <= TT + 1; ++i) {
        const int pc = i & 1, pn = pc ^ 1;
        if (gid == 0) {
            if (i <= TT - 1) {                           // h1_i (2 rows)
                float2 xn[2];
                const bool pf = (i + 1 <= TT - 1);
                if (pf) {
                    #pragma unroll
                    for (int r = 0; r < 2; ++r)
                        xn[r] = *reinterpret_cast<const float2*>(
                            &XPbuf[((size_t)(r0 + rp*2 + r) * TT + (i+1)) * HH + u0]);
                }
                unsigned long long a[4] = {0ull, 0ull, 0ull, 0ull};
                accum4_g1(a, &sH1[pn][rp*2][0], w);
                if (act) {
                    float2 o0, o1;
                    o0.x = tanh_f(hsum2(a[0]) + xcur[0].x);
                    o0.y = tanh_f(hsum2(a[2]) + xcur[0].y);
                    o1.x = tanh_f(hsum2(a[1]) + xcur[1].x);
                    o1.y = tanh_f(hsum2(a[3]) + xcur[1].y);
                    *reinterpret_cast<float2*>(&sH1[pc][rp*2    ][u0]) = o0;
                    *reinterpret_cast<float2*>(&sH1[pc][rp*2 + 1][u0]) = o1;
                }
                if (pf) { xcur[0] = xn[0]; xcur[1] = xn[1]; }
            }
            BAR_SYNC(2, 192);
        } else if (gid == 1) {
            if (i >= 1 && i <= TT) {                     // p_{i-1} (4 rows)
                unsigned long long a[8];
                #pragma unroll
                for (int n = 0; n < 8; ++n) a[n] = 0ull;
                accum8_h(a, &sH1[pn][0][0], w);
                if (act) {
                    #pragma unroll
                    for (int r = 0; r < ROWS; ++r) {
                        float2 v;
                        v.x = hsum2(a[r])   + bj0;
                        v.y = hsum2(a[4+r]) + bj1;
                        *reinterpret_cast<float2*>(&sP[pn][r][u0]) = v;
                    }
                }
            }
            BAR_SYNC(3, 128);   // release G2b first (longer consumer chain)
            BAR_SYNC(2, 192);
        } else {
            if (i >= 2) {                                // h2_{i-2} (4 rows)
                float2 pv[4];
                #pragma unroll
                for (int r = 0; r < ROWS; ++r)
                    pv[r] = *reinterpret_cast<const float2*>(&sP[pc][r][u0]);
                unsigned long long a[8];
                #pragma unroll
                for (int n = 0; n < 8; ++n) a[n] = 0ull;
                accum8_h(a, &sH2[pn][0][0], w);
                if (act) {
                    #pragma unroll
                    for (int r = 0; r < ROWS; ++r) {
                        float2 v;
                        v.x = tanh_f(hsum2(a[r])   + pv[r].x);
                        v.y = tanh_f(hsum2(a[4+r]) + pv[r].y);
                        *reinterpret_cast<float2*>(&sH2[pc][r][u0]) = v;
                    }
                }
            }
            BAR_SYNC(3, 128);
        }
    }
    __syncthreads();

    // h1_511 in sH1[1], h2_511 in sH2[1] (both parity 1).
    float* outVec = out;                      // [512]
    float* outH1  = out + BB;                 // [512,100]
    float* outH2  = out + BB + BB*HH;         // [512,100]

    for (int idx = tid; idx < ROWS*HH; idx += NTHR) {
        int r = idx / HH, uu = idx % HH;
        outH1[(size_t)(r0 + r)*HH + uu] = sH1[1][r][uu];
        outH2[(size_t)(r0 + r)*HH + uu] = sH2[1][r][uu];
    }

    // Output head: out[r] = h2_T[r] . Wo + bo  (warp 0).
    if (tid < 32) {
        #pragma unroll
        for (int r = 0; r < ROWS; ++r) {
            float v = 0.f;
            #pragma unroll
            for (int mm = 0; mm < 4; ++mm) {
                int uu = mm*32 + tid;
                if (uu < HH) v += sH2[1][r][uu] * Wo[uu];
            }
            #pragma unroll
            for (int off = 16; off; off >>= 1)
                v += __shfl_down_sync(0xffffffffu, v, off);
            if (tid == 0) outVec[r0 + r] = v + Bo[0];
        }
    }
}

extern "C" void kernel_launch(void* const* d_in, const int* in_sizes, int n_in,
                              void* d_out, int out_size) {
    (void)in_sizes; (void)n_in; (void)out_size;
    const float* X   = (const float*)d_in[0];
    const float* W1x = (const float*)d_in[1];
    const float* W1h = (const float*)d_in[2];
    const float* B1  = (const float*)d_in[3];
    const float* W2x = (const float*)d_in[4];
    const float* W2h = (const float*)d_in[5];
    const float* B2  = (const float*)d_in[6];
    const float* Wo  = (const float*)d_in[7];
    const float* Bo  = (const float*)d_in[8];

    dim3 pgrid(4, BB);
    xp_prepass<<<pgrid, 256>>>(X, W1x, B1);
    drnn_kernel<<<BB/ROWS, NTHR>>>(W1h, W2x, W2h, B2, Wo, Bo, (float*)d_out);
}